// round 15
// baseline (speedup 1.0000x reference)
#include <cuda_runtime.h>

// Problem constants (fixed-shape problem)
#define NB      32
#define NSITES  65536
#define NNGB    13
#define DIM     3
#define NG      48
#define KDIM    (NG * DIM)             // 144
#define NPREP   16
#define TSITES  128                    // sites per transpose tile
#define NTRANS  (NSITES / TSITES)      // 512 transpose tiles
#define NTILE   2048                   // conv tiles (32 sites each)
#define GRID    444                    // 148 SMs x 3 blocks, all co-resident
#define THREADS 256

// Scratch (device-global: allocation-free rule)
__device__ __align__(16) float g_InT[NSITES * NB];   // 8 MB site-major transpose
__device__ float    g_Wpart[NPREP][DIM * NNGB];
__device__ unsigned g_tA, g_tB, g_barrier, g_done;   // zero-init, self-reset

__device__ __forceinline__ void cp_async4(unsigned smem_addr, const void* gptr) {
    asm volatile("cp.async.ca.shared.global [%0], [%1], 4;"
                 :: "r"(smem_addr), "l"(gptr));
}
__device__ __forceinline__ void cp_async_commit() {
    asm volatile("cp.async.commit_group;");
}
__device__ __forceinline__ void cp_async_wait_all() {
    asm volatile("cp.async.wait_group 0;");
}

// Shared memory union (single 16512B buffer, phase-disjoint):
//  transpose: tile[32][129]                  = 16512B
//  prep     : B[144*13]@0, sW[39]@7488       =  7648B
//  conv     : Wm[40]@0 (160B) | sidx[2][416]@160 (3328B) | sout[3192]@3488 (12768B)
#define SMEM_BYTES 16512

__global__ __launch_bounds__(THREADS, 3)
void fused_all_kernel(const float* __restrict__ In,
                      const float* __restrict__ wtVC,
                      const float* __restrict__ gdiags,
                      const int*   __restrict__ GnnPerms,
                      const int*   __restrict__ NNsites,
                      float*       __restrict__ out) {
    __shared__ __align__(16) unsigned char s_raw[SMEM_BYTES];
    __shared__ unsigned s_tk;
    int tid  = threadIdx.x;
    int w    = tid >> 5;
    int lane = tid & 31;

    // ================= Phase A0: Wmean partials (blocks 0..15) =============
    if (blockIdx.x < NPREP) {
        int p = blockIdx.x;
        float* B  = (float*)s_raw;                 // [144][13]
        float* sW = (float*)(s_raw + 7488);        // 39 accumulators
        if (tid < DIM * NNGB) sW[tid] = 0.f;
        for (int i = tid; i < KDIM * NNGB; i += THREADS) {
            int k = i / NNGB, j = i % NNGB;
            B[i] = wtVC[(k % 3) * NNGB + GnnPerms[(k / 3) * NNGB + j]];
        }
        __syncthreads();
        for (int rl = w; rl < 9; rl += 8) {        // 9 gdiags rows, 8 warps
            int r = p * 9 + rl;
            float acc[NNGB];
            #pragma unroll
            for (int j = 0; j < NNGB; j++) acc[j] = 0.f;
            for (int k = lane; k < KDIM; k += 32) {
                float gv = gdiags[r * KDIM + k];
                #pragma unroll
                for (int j = 0; j < NNGB; j++) acc[j] += gv * B[k * NNGB + j];
            }
            #pragma unroll
            for (int j = 0; j < NNGB; j++) {
                #pragma unroll
                for (int o = 16; o > 0; o >>= 1)
                    acc[j] += __shfl_xor_sync(0xffffffffu, acc[j], o);
            }
            if (lane == 0) {
                int d = r % 3;
                #pragma unroll
                for (int j = 0; j < NNGB; j++)
                    atomicAdd(&sW[d * NNGB + j], acc[j]);
            }
        }
        __syncthreads();
        if (tid < DIM * NNGB) g_Wpart[p][tid] = sW[tid];
    }

    // ================= Phase A1: ticketed transpose =========================
    {
        float* tile = (float*)s_raw;               // [32][129] padded
        for (;;) {
            __syncthreads();                       // protect s_tk + tile reuse
            if (tid == 0) s_tk = atomicAdd(&g_tA, 1);
            __syncthreads();
            unsigned t = s_tk;
            if (t >= NTRANS) break;
            int s0 = t * TSITES;
            #pragma unroll
            for (int k = 0; k < 16; k++) {
                int i = tid + (k << 8);
                int b = i >> 7, x = i & 127;
                tile[b * 129 + x] = In[b * NSITES + s0 + x];    // coalesced
            }
            __syncthreads();
            #pragma unroll
            for (int k = 0; k < 16; k++) {
                int i  = tid + (k << 8);
                int sl = i >> 5, b = i & 31;
                g_InT[(s0 + sl) * NB + b] = tile[b * 129 + sl]; // coalesced
            }
        }
    }

    // ================= Grid barrier (all 444 blocks co-resident) ============
    __syncthreads();
    if (tid == 0) {
        __threadfence();                 // release g_InT / g_Wpart writes
        atomicAdd(&g_barrier, 1);
        while (*((volatile unsigned*)&g_barrier) < GRID) __nanosleep(64);
        __threadfence();                 // acquire others' writes
    }
    __syncthreads();

    // ================= Phase B: ticketed, pipelined conv (r14 core) =========
    float* Wm   = (float*)s_raw;                   // 39 floats
    int*   sidx = (int*)(s_raw + 160);             // [2][13*32]
    float* sout = (float*)(s_raw + 3488);          // d*1064 + b*33 + si

    if (tid < DIM * NNGB) {
        float s = 0.f;
        #pragma unroll
        for (int p = 0; p < NPREP; p++) s += g_Wpart[p][tid];
        Wm[tid] = s * (1.0f / (float)NG);
    }

    // -- prologue: first ticket + plain sidx load ---------------------------
    if (tid == 0) s_tk = atomicAdd(&g_tB, 1);
    __syncthreads();                               // (A) s_tk + Wm visible
    unsigned t = s_tk;
    if (t < NTILE) {
        for (int i = tid; i < NNGB * 32; i += THREADS) {
            int j = i >> 5, si = i & 31;
            sidx[i] = NNsites[j * NSITES + t * 32 + si];
        }
    }
    if (tid == 0) s_tk = atomicAdd(&g_tB, 1);      // next ticket
    __syncthreads();                               // (B)

    int site = (w << 2) + (lane >> 3);   // 0..31
    int c    = lane & 7;                 // 16B chunk -> batches 4c..4c+3
    const float4* __restrict__ InT4 = (const float4*)g_InT;

    int cur = 0;
    while (t < NTILE) {
        unsigned tn = s_tk;              // stable since (B)/(E)
        int s0 = t * 32;

        // 1) current tile: indices, then all 13 gathers back-to-back
        int idx[NNGB];
        #pragma unroll
        for (int j = 0; j < NNGB; j++) idx[j] = sidx[cur * 416 + j * 32 + site];

        float4 v[NNGB];
        #pragma unroll
        for (int j = 0; j < NNGB; j++) v[j] = __ldg(&InT4[idx[j] * 8 + c]);

        // 2) prefetch next tile's indices (cp.async: zero register cost)
        if (tn < NTILE) {
            for (int i = tid; i < NNGB * 32; i += THREADS) {
                int j = i >> 5, si = i & 31;
                cp_async4((unsigned)__cvta_generic_to_shared(
                              &sidx[(cur ^ 1) * 416 + i]),
                          &NNsites[j * NSITES + tn * 32 + si]);
            }
        }
        cp_async_commit();

        // 3) contraction
        float4 a0 = make_float4(0.f, 0.f, 0.f, 0.f);
        float4 a1 = a0, a2 = a0;
        #pragma unroll
        for (int j = 0; j < NNGB; j++) {
            float w0 = Wm[j], w1 = Wm[NNGB + j], w2 = Wm[2 * NNGB + j];
            a0.x += w0 * v[j].x; a0.y += w0 * v[j].y; a0.z += w0 * v[j].z; a0.w += w0 * v[j].w;
            a1.x += w1 * v[j].x; a1.y += w1 * v[j].y; a1.z += w1 * v[j].z; a1.w += w1 * v[j].w;
            a2.x += w2 * v[j].x; a2.y += w2 * v[j].y; a2.z += w2 * v[j].z; a2.w += w2 * v[j].w;
        }

        // 4) epilogue: stage conflict-free, then 3 STG.128 per thread
        int b0 = c << 2;
        sout[0 * 1064 + (b0 + 0) * 33 + site] = a0.x;
        sout[0 * 1064 + (b0 + 1) * 33 + site] = a0.y;
        sout[0 * 1064 + (b0 + 2) * 33 + site] = a0.z;
        sout[0 * 1064 + (b0 + 3) * 33 + site] = a0.w;
        sout[1 * 1064 + (b0 + 0) * 33 + site] = a1.x;
        sout[1 * 1064 + (b0 + 1) * 33 + site] = a1.y;
        sout[1 * 1064 + (b0 + 2) * 33 + site] = a1.z;
        sout[1 * 1064 + (b0 + 3) * 33 + site] = a1.w;
        sout[2 * 1064 + (b0 + 0) * 33 + site] = a2.x;
        sout[2 * 1064 + (b0 + 1) * 33 + site] = a2.y;
        sout[2 * 1064 + (b0 + 2) * 33 + site] = a2.z;
        sout[2 * 1064 + (b0 + 3) * 33 + site] = a2.w;
        __syncthreads();                           // (D)

        #pragma unroll
        for (int k = 0; k < 3; k++) {
            int f4  = tid + (k << 8);
            int p   = f4 & 7;
            int row = f4 >> 3;         // b*3+d
            int d   = row % 3;
            int b   = row / 3;
            int si  = p << 2;
            float4 o;
            o.x = sout[d * 1064 + b * 33 + si];
            o.y = sout[d * 1064 + b * 33 + si + 1];
            o.z = sout[d * 1064 + b * 33 + si + 2];
            o.w = sout[d * 1064 + b * 33 + si + 3];
            ((float4*)(out + row * NSITES + s0))[p] = o;
        }

        // 5) advance: next-next ticket, wait prefetch, publish
        if (tid == 0 && tn < NTILE) s_tk = atomicAdd(&g_tB, 1);
        cp_async_wait_all();
        __syncthreads();                           // (E)
        cur ^= 1;
        t = tn;
    }

    // ================= Counter self-reset (replay-safe) =====================
    __syncthreads();
    if (tid == 0) {
        unsigned d = atomicAdd(&g_done, 1);
        if (d == GRID - 1) {
            g_tA = 0; g_tB = 0; g_barrier = 0;
            __threadfence();
            g_done = 0;
        }
    }
}

// ---------------------------------------------------------------------------
// Launch: In, wtVC, gdiags, GnnPerms, NNsites (metadata order). ONE kernel.
// ---------------------------------------------------------------------------
extern "C" void kernel_launch(void* const* d_in, const int* in_sizes, int n_in,
                              void* d_out, int out_size) {
    const float* In       = (const float*)d_in[0];
    const float* wtVC     = (const float*)d_in[1];
    const float* gdiags   = (const float*)d_in[2];
    const int*   GnnPerms = (const int*)  d_in[3];
    const int*   NNsites  = (const int*)  d_in[4];
    float*       out      = (float*)d_out;

    fused_all_kernel<<<GRID, THREADS>>>(In, wtVC, gdiags, GnnPerms, NNsites, out);
}

// round 16
// speedup vs baseline: 1.0154x; 1.0154x over previous
#include <cuda_runtime.h>
#include <cuda_fp16.h>

// Problem constants (fixed-shape problem)
#define NB      32
#define NSITES  65536
#define NNGB    13
#define DIM     3
#define NG      48
#define KDIM    (NG * DIM)             // 144
#define NPREP   16
#define TSITES  128                    // sites per transpose tile
#define NTRANS  (NSITES / TSITES)      // 512 transpose tiles
#define NTILE   2048                   // conv tiles (32 sites each)
#define GRID    444                    // 148 SMs x 3 blocks, all co-resident
#define THREADS 256

// Scratch (device-global: allocation-free rule)
__device__ __align__(16) __half g_InTh[NSITES * NB]; // 4 MB fp16 site-major
__device__ float    g_Wpart[NPREP][DIM * NNGB];
__device__ unsigned g_tA, g_tB, g_barrier, g_done;   // zero-init, self-reset

__device__ __forceinline__ void cp_async4(unsigned smem_addr, const void* gptr) {
    asm volatile("cp.async.ca.shared.global [%0], [%1], 4;"
                 :: "r"(smem_addr), "l"(gptr));
}
__device__ __forceinline__ void cp_async_commit() {
    asm volatile("cp.async.commit_group;");
}
__device__ __forceinline__ void cp_async_wait_all() {
    asm volatile("cp.async.wait_group 0;");
}

// Shared memory union (single 16512B buffer, phase-disjoint):
//  transpose: tile[32][129] fp32              = 16512B
//  prep     : B[144*13]@0, sW[39]@7488        =  7648B
//  conv     : Wm[40]@0 | sidx[2][416]@160 | sout[3192]@3488
#define SMEM_BYTES 16512

__global__ __launch_bounds__(THREADS, 3)
void fused_all_kernel(const float* __restrict__ In,
                      const float* __restrict__ wtVC,
                      const float* __restrict__ gdiags,
                      const int*   __restrict__ GnnPerms,
                      const int*   __restrict__ NNsites,
                      float*       __restrict__ out) {
    __shared__ __align__(16) unsigned char s_raw[SMEM_BYTES];
    __shared__ unsigned s_tk;
    int tid  = threadIdx.x;
    int w    = tid >> 5;
    int lane = tid & 31;

    // ================= Phase A0: Wmean partials (blocks 0..15) =============
    if (blockIdx.x < NPREP) {
        int p = blockIdx.x;
        float* B  = (float*)s_raw;                 // [144][13]
        float* sW = (float*)(s_raw + 7488);        // 39 accumulators
        if (tid < DIM * NNGB) sW[tid] = 0.f;
        for (int i = tid; i < KDIM * NNGB; i += THREADS) {
            int k = i / NNGB, j = i % NNGB;
            B[i] = wtVC[(k % 3) * NNGB + GnnPerms[(k / 3) * NNGB + j]];
        }
        __syncthreads();
        for (int rl = w; rl < 9; rl += 8) {        // 9 gdiags rows, 8 warps
            int r = p * 9 + rl;
            float acc[NNGB];
            #pragma unroll
            for (int j = 0; j < NNGB; j++) acc[j] = 0.f;
            for (int k = lane; k < KDIM; k += 32) {
                float gv = gdiags[r * KDIM + k];
                #pragma unroll
                for (int j = 0; j < NNGB; j++) acc[j] += gv * B[k * NNGB + j];
            }
            #pragma unroll
            for (int j = 0; j < NNGB; j++) {
                #pragma unroll
                for (int o = 16; o > 0; o >>= 1)
                    acc[j] += __shfl_xor_sync(0xffffffffu, acc[j], o);
            }
            if (lane == 0) {
                int d = r % 3;
                #pragma unroll
                for (int j = 0; j < NNGB; j++)
                    atomicAdd(&sW[d * NNGB + j], acc[j]);
            }
        }
        __syncthreads();
        if (tid < DIM * NNGB) g_Wpart[p][tid] = sW[tid];
    }

    // ================= Phase A1: ticketed transpose (fp32 -> fp16) =========
    {
        float* tile = (float*)s_raw;               // [32][129] padded
        for (;;) {
            __syncthreads();                       // protect s_tk + tile reuse
            if (tid == 0) s_tk = atomicAdd(&g_tA, 1);
            __syncthreads();
            unsigned t = s_tk;
            if (t >= NTRANS) break;
            int s0 = t * TSITES;
            #pragma unroll
            for (int k = 0; k < 16; k++) {
                int i = tid + (k << 8);
                int b = i >> 7, x = i & 127;
                tile[b * 129 + x] = In[b * NSITES + s0 + x];    // coalesced
            }
            __syncthreads();
            #pragma unroll
            for (int k = 0; k < 16; k++) {
                int i  = tid + (k << 8);
                int sl = i >> 5, b = i & 31;
                g_InTh[(s0 + sl) * NB + b] =
                    __float2half(tile[b * 129 + sl]);           // coalesced 2B
            }
        }
    }

    // ================= Grid barrier (all 444 blocks co-resident) ============
    __syncthreads();
    if (tid == 0) {
        __threadfence();                 // release g_InTh / g_Wpart writes
        atomicAdd(&g_barrier, 1);
        while (*((volatile unsigned*)&g_barrier) < GRID) __nanosleep(64);
        __threadfence();                 // acquire others' writes
    }
    __syncthreads();

    // ================= Phase B: ticketed, pipelined conv (fp16 gather) ======
    float* Wm   = (float*)s_raw;                   // 39 floats
    int*   sidx = (int*)(s_raw + 160);             // [2][13*32]
    float* sout = (float*)(s_raw + 3488);          // d*1064 + b*33 + si

    if (tid < DIM * NNGB) {
        float s = 0.f;
        #pragma unroll
        for (int p = 0; p < NPREP; p++) s += g_Wpart[p][tid];
        Wm[tid] = s * (1.0f / (float)NG);
    }

    // -- prologue: first ticket + plain sidx load ---------------------------
    if (tid == 0) s_tk = atomicAdd(&g_tB, 1);
    __syncthreads();                               // (A) s_tk + Wm visible
    unsigned t = s_tk;
    if (t < NTILE) {
        for (int i = tid; i < NNGB * 32; i += THREADS) {
            int j = i >> 5, si = i & 31;
            sidx[i] = NNsites[j * NSITES + t * 32 + si];
        }
    }
    if (tid == 0) s_tk = atomicAdd(&g_tB, 1);      // next ticket
    __syncthreads();                               // (B)

    int site = (w << 2) + (lane >> 3);   // 0..31
    int c    = lane & 7;                 // 8B chunk -> batches 4c..4c+3 (fp16)
    const uint2* __restrict__ InT2h = (const uint2*)g_InTh;  // row = 8 uint2

    int cur = 0;
    while (t < NTILE) {
        unsigned tn = s_tk;              // stable since (B)/(E)
        int s0 = t * 32;

        // 1) current tile: indices, then all 13 LDG.64 back-to-back.
        //    fp16 row = 64B -> each 128B line carries TWO site-rows: total
        //    wavefront count is HALF the fp32 version.
        int idx[NNGB];
        #pragma unroll
        for (int j = 0; j < NNGB; j++) idx[j] = sidx[cur * 416 + j * 32 + site];

        uint2 v[NNGB];
        #pragma unroll
        for (int j = 0; j < NNGB; j++) v[j] = __ldg(&InT2h[idx[j] * 8 + c]);

        // 2) prefetch next tile's indices (cp.async: zero register cost)
        if (tn < NTILE) {
            for (int i = tid; i < NNGB * 32; i += THREADS) {
                int j = i >> 5, si = i & 31;
                cp_async4((unsigned)__cvta_generic_to_shared(
                              &sidx[(cur ^ 1) * 416 + i]),
                          &NNsites[j * NSITES + tn * 32 + si]);
            }
        }
        cp_async_commit();

        // 3) contraction (convert half2 -> float2, accumulate fp32)
        float4 a0 = make_float4(0.f, 0.f, 0.f, 0.f);
        float4 a1 = a0, a2 = a0;
        #pragma unroll
        for (int j = 0; j < NNGB; j++) {
            float2 lo = __half22float2(*reinterpret_cast<const __half2*>(&v[j].x));
            float2 hi = __half22float2(*reinterpret_cast<const __half2*>(&v[j].y));
            float w0 = Wm[j], w1 = Wm[NNGB + j], w2 = Wm[2 * NNGB + j];
            a0.x += w0 * lo.x; a0.y += w0 * lo.y; a0.z += w0 * hi.x; a0.w += w0 * hi.y;
            a1.x += w1 * lo.x; a1.y += w1 * lo.y; a1.z += w1 * hi.x; a1.w += w1 * hi.y;
            a2.x += w2 * lo.x; a2.y += w2 * lo.y; a2.z += w2 * hi.x; a2.w += w2 * hi.y;
        }

        // 4) epilogue: stage conflict-free, then 3 STG.128 per thread
        int b0 = c << 2;
        sout[0 * 1064 + (b0 + 0) * 33 + site] = a0.x;
        sout[0 * 1064 + (b0 + 1) * 33 + site] = a0.y;
        sout[0 * 1064 + (b0 + 2) * 33 + site] = a0.z;
        sout[0 * 1064 + (b0 + 3) * 33 + site] = a0.w;
        sout[1 * 1064 + (b0 + 0) * 33 + site] = a1.x;
        sout[1 * 1064 + (b0 + 1) * 33 + site] = a1.y;
        sout[1 * 1064 + (b0 + 2) * 33 + site] = a1.z;
        sout[1 * 1064 + (b0 + 3) * 33 + site] = a1.w;
        sout[2 * 1064 + (b0 + 0) * 33 + site] = a2.x;
        sout[2 * 1064 + (b0 + 1) * 33 + site] = a2.y;
        sout[2 * 1064 + (b0 + 2) * 33 + site] = a2.z;
        sout[2 * 1064 + (b0 + 3) * 33 + site] = a2.w;
        __syncthreads();                           // (D)

        #pragma unroll
        for (int k = 0; k < 3; k++) {
            int f4  = tid + (k << 8);
            int p   = f4 & 7;
            int row = f4 >> 3;         // b*3+d
            int d   = row % 3;
            int b   = row / 3;
            int si  = p << 2;
            float4 o;
            o.x = sout[d * 1064 + b * 33 + si];
            o.y = sout[d * 1064 + b * 33 + si + 1];
            o.z = sout[d * 1064 + b * 33 + si + 2];
            o.w = sout[d * 1064 + b * 33 + si + 3];
            ((float4*)(out + row * NSITES + s0))[p] = o;
        }

        // 5) advance: next-next ticket, wait prefetch, publish
        if (tid == 0 && tn < NTILE) s_tk = atomicAdd(&g_tB, 1);
        cp_async_wait_all();
        __syncthreads();                           // (E)
        cur ^= 1;
        t = tn;
    }

    // ================= Counter self-reset (replay-safe) =====================
    __syncthreads();
    if (tid == 0) {
        unsigned d = atomicAdd(&g_done, 1);
        if (d == GRID - 1) {
            g_tA = 0; g_tB = 0; g_barrier = 0;
            __threadfence();
            g_done = 0;
        }
    }
}

// ---------------------------------------------------------------------------
// Launch: In, wtVC, gdiags, GnnPerms, NNsites (metadata order). ONE kernel.
// ---------------------------------------------------------------------------
extern "C" void kernel_launch(void* const* d_in, const int* in_sizes, int n_in,
                              void* d_out, int out_size) {
    const float* In       = (const float*)d_in[0];
    const float* wtVC     = (const float*)d_in[1];
    const float* gdiags   = (const float*)d_in[2];
    const int*   GnnPerms = (const int*)  d_in[3];
    const int*   NNsites  = (const int*)  d_in[4];
    float*       out      = (float*)d_out;

    fused_all_kernel<<<GRID, THREADS>>>(In, wtVC, gdiags, GnnPerms, NNsites, out);
}

// round 17
// speedup vs baseline: 1.0313x; 1.0157x over previous
#include <cuda_runtime.h>
#include <cuda_fp16.h>

// Problem constants (fixed-shape problem)
#define NB      32
#define NSITES  65536
#define NNGB    13
#define DIM     3
#define NG      48
#define KDIM    (NG * DIM)             // 144
#define NPREP   16
#define TSITES  128                    // sites per transpose tile
#define NTRANS  (NSITES / TSITES)      // 512 transpose tiles
#define NTILE   2048                   // conv tiles (32 sites each)
#define GRID    592                    // 148 SMs x 4 blocks, all co-resident
#define THREADS 256
#define JB1     7                      // first gather batch
#define JB2     6                      // second gather batch

// Scratch (device-global: allocation-free rule)
__device__ __align__(16) __half g_InTh[NSITES * NB]; // 4 MB fp16 site-major
__device__ float    g_Wpart[NPREP][DIM * NNGB];
__device__ unsigned g_tA, g_tB, g_barrier, g_done;   // zero-init, self-reset

__device__ __forceinline__ void cp_async4(unsigned smem_addr, const void* gptr) {
    asm volatile("cp.async.ca.shared.global [%0], [%1], 4;"
                 :: "r"(smem_addr), "l"(gptr));
}
__device__ __forceinline__ void cp_async_commit() {
    asm volatile("cp.async.commit_group;");
}
__device__ __forceinline__ void cp_async_wait_all() {
    asm volatile("cp.async.wait_group 0;");
}

// Shared memory union (single 16512B buffer, phase-disjoint):
//  transpose: tile[32][129] fp32              = 16512B
//  prep     : B[144*13]@0, sW[39]@7488        =  7648B
//  conv     : Wm[40]@0 | sidx[2][416]@160 | sout[3192]@3488
#define SMEM_BYTES 16512

__global__ __launch_bounds__(THREADS, 4)    // 64-reg cap -> 4 blocks/SM
void fused_all_kernel(const float* __restrict__ In,
                      const float* __restrict__ wtVC,
                      const float* __restrict__ gdiags,
                      const int*   __restrict__ GnnPerms,
                      const int*   __restrict__ NNsites,
                      float*       __restrict__ out) {
    __shared__ __align__(16) unsigned char s_raw[SMEM_BYTES];
    __shared__ unsigned s_tk;
    int tid  = threadIdx.x;
    int w    = tid >> 5;
    int lane = tid & 31;

    // ================= Phase A0: Wmean partials (blocks 0..15) =============
    if (blockIdx.x < NPREP) {
        int p = blockIdx.x;
        float* B  = (float*)s_raw;                 // [144][13]
        float* sW = (float*)(s_raw + 7488);        // 39 accumulators
        if (tid < DIM * NNGB) sW[tid] = 0.f;
        for (int i = tid; i < KDIM * NNGB; i += THREADS) {
            int k = i / NNGB, j = i % NNGB;
            B[i] = wtVC[(k % 3) * NNGB + GnnPerms[(k / 3) * NNGB + j]];
        }
        __syncthreads();
        for (int rl = w; rl < 9; rl += 8) {        // 9 gdiags rows, 8 warps
            int r = p * 9 + rl;
            float acc[NNGB];
            #pragma unroll
            for (int j = 0; j < NNGB; j++) acc[j] = 0.f;
            for (int k = lane; k < KDIM; k += 32) {
                float gv = gdiags[r * KDIM + k];
                #pragma unroll
                for (int j = 0; j < NNGB; j++) acc[j] += gv * B[k * NNGB + j];
            }
            #pragma unroll
            for (int j = 0; j < NNGB; j++) {
                #pragma unroll
                for (int o = 16; o > 0; o >>= 1)
                    acc[j] += __shfl_xor_sync(0xffffffffu, acc[j], o);
            }
            if (lane == 0) {
                int d = r % 3;
                #pragma unroll
                for (int j = 0; j < NNGB; j++)
                    atomicAdd(&sW[d * NNGB + j], acc[j]);
            }
        }
        __syncthreads();
        if (tid < DIM * NNGB) g_Wpart[p][tid] = sW[tid];
    }

    // ================= Phase A1: ticketed transpose (fp32 -> fp16) =========
    {
        float* tile = (float*)s_raw;               // [32][129] padded
        for (;;) {
            __syncthreads();                       // protect s_tk + tile reuse
            if (tid == 0) s_tk = atomicAdd(&g_tA, 1);
            __syncthreads();
            unsigned t = s_tk;
            if (t >= NTRANS) break;
            int s0 = t * TSITES;
            #pragma unroll
            for (int k = 0; k < 16; k++) {
                int i = tid + (k << 8);
                int b = i >> 7, x = i & 127;
                tile[b * 129 + x] = In[b * NSITES + s0 + x];    // coalesced
            }
            __syncthreads();
            #pragma unroll
            for (int k = 0; k < 16; k++) {
                int i  = tid + (k << 8);
                int sl = i >> 5, b = i & 31;
                g_InTh[(s0 + sl) * NB + b] =
                    __float2half(tile[b * 129 + sl]);           // coalesced 2B
            }
        }
    }

    // ================= Grid barrier (all 592 blocks co-resident) ============
    __syncthreads();
    if (tid == 0) {
        __threadfence();                 // release g_InTh / g_Wpart writes
        atomicAdd(&g_barrier, 1);
        while (*((volatile unsigned*)&g_barrier) < GRID) __nanosleep(64);
        __threadfence();                 // acquire others' writes
    }
    __syncthreads();

    // ================= Phase B: ticketed, pipelined conv (fp16, 7+6) =======
    float* Wm   = (float*)s_raw;                   // 39 floats
    int*   sidx = (int*)(s_raw + 160);             // [2][13*32]
    float* sout = (float*)(s_raw + 3488);          // d*1064 + b*33 + si

    if (tid < DIM * NNGB) {
        float s = 0.f;
        #pragma unroll
        for (int p = 0; p < NPREP; p++) s += g_Wpart[p][tid];
        Wm[tid] = s * (1.0f / (float)NG);
    }

    // -- prologue: first ticket + plain sidx load ---------------------------
    if (tid == 0) s_tk = atomicAdd(&g_tB, 1);
    __syncthreads();                               // (A) s_tk + Wm visible
    unsigned t = s_tk;
    if (t < NTILE) {
        for (int i = tid; i < NNGB * 32; i += THREADS) {
            int j = i >> 5, si = i & 31;
            sidx[i] = NNsites[j * NSITES + t * 32 + si];
        }
    }
    if (tid == 0) s_tk = atomicAdd(&g_tB, 1);      // next ticket
    __syncthreads();                               // (B)

    int site = (w << 2) + (lane >> 3);   // 0..31
    int c    = lane & 7;                 // 8B chunk -> batches 4c..4c+3 (fp16)
    const uint2* __restrict__ InT2h = (const uint2*)g_InTh;  // row = 8 uint2

    int cur = 0;
    while (t < NTILE) {
        unsigned tn = s_tk;              // stable since (B)/(E)
        int s0 = t * 32;

        int idx[NNGB];
        #pragma unroll
        for (int j = 0; j < NNGB; j++) idx[j] = sidx[cur * 416 + j * 32 + site];

        // 2) prefetch next tile's indices (cp.async: zero register cost)
        if (tn < NTILE) {
            for (int i = tid; i < NNGB * 32; i += THREADS) {
                int j = i >> 5, si = i & 31;
                cp_async4((unsigned)__cvta_generic_to_shared(
                              &sidx[(cur ^ 1) * 416 + i]),
                          &NNsites[j * NSITES + tn * 32 + si]);
            }
        }
        cp_async_commit();

        float4 a0 = make_float4(0.f, 0.f, 0.f, 0.f);
        float4 a1 = a0, a2 = a0;

        // batch 1: 7 LDG.64 back-to-back, then consume (frees v1 regs)
        {
            uint2 v[JB1];
            #pragma unroll
            for (int j = 0; j < JB1; j++) v[j] = __ldg(&InT2h[idx[j] * 8 + c]);
            #pragma unroll
            for (int j = 0; j < JB1; j++) {
                float2 lo = __half22float2(*reinterpret_cast<const __half2*>(&v[j].x));
                float2 hi = __half22float2(*reinterpret_cast<const __half2*>(&v[j].y));
                float w0 = Wm[j], w1 = Wm[NNGB + j], w2 = Wm[2 * NNGB + j];
                a0.x += w0 * lo.x; a0.y += w0 * lo.y; a0.z += w0 * hi.x; a0.w += w0 * hi.y;
                a1.x += w1 * lo.x; a1.y += w1 * lo.y; a1.z += w1 * hi.x; a1.w += w1 * hi.y;
                a2.x += w2 * lo.x; a2.y += w2 * lo.y; a2.z += w2 * hi.x; a2.w += w2 * hi.y;
            }
        }
        // batch 2: remaining 6
        {
            uint2 v[JB2];
            #pragma unroll
            for (int j = 0; j < JB2; j++) v[j] = __ldg(&InT2h[idx[JB1 + j] * 8 + c]);
            #pragma unroll
            for (int j = 0; j < JB2; j++) {
                int jj = JB1 + j;
                float2 lo = __half22float2(*reinterpret_cast<const __half2*>(&v[j].x));
                float2 hi = __half22float2(*reinterpret_cast<const __half2*>(&v[j].y));
                float w0 = Wm[jj], w1 = Wm[NNGB + jj], w2 = Wm[2 * NNGB + jj];
                a0.x += w0 * lo.x; a0.y += w0 * lo.y; a0.z += w0 * hi.x; a0.w += w0 * hi.y;
                a1.x += w1 * lo.x; a1.y += w1 * lo.y; a1.z += w1 * hi.x; a1.w += w1 * hi.y;
                a2.x += w2 * lo.x; a2.y += w2 * lo.y; a2.z += w2 * hi.x; a2.w += w2 * hi.y;
            }
        }

        // 4) epilogue: stage conflict-free, then 3 STG.128 per thread
        int b0 = c << 2;
        sout[0 * 1064 + (b0 + 0) * 33 + site] = a0.x;
        sout[0 * 1064 + (b0 + 1) * 33 + site] = a0.y;
        sout[0 * 1064 + (b0 + 2) * 33 + site] = a0.z;
        sout[0 * 1064 + (b0 + 3) * 33 + site] = a0.w;
        sout[1 * 1064 + (b0 + 0) * 33 + site] = a1.x;
        sout[1 * 1064 + (b0 + 1) * 33 + site] = a1.y;
        sout[1 * 1064 + (b0 + 2) * 33 + site] = a1.z;
        sout[1 * 1064 + (b0 + 3) * 33 + site] = a1.w;
        sout[2 * 1064 + (b0 + 0) * 33 + site] = a2.x;
        sout[2 * 1064 + (b0 + 1) * 33 + site] = a2.y;
        sout[2 * 1064 + (b0 + 2) * 33 + site] = a2.z;
        sout[2 * 1064 + (b0 + 3) * 33 + site] = a2.w;
        __syncthreads();                           // (D)

        #pragma unroll
        for (int k = 0; k < 3; k++) {
            int f4  = tid + (k << 8);
            int p   = f4 & 7;
            int row = f4 >> 3;         // b*3+d
            int d   = row % 3;
            int b   = row / 3;
            int si  = p << 2;
            float4 o;
            o.x = sout[d * 1064 + b * 33 + si];
            o.y = sout[d * 1064 + b * 33 + si + 1];
            o.z = sout[d * 1064 + b * 33 + si + 2];
            o.w = sout[d * 1064 + b * 33 + si + 3];
            ((float4*)(out + row * NSITES + s0))[p] = o;
        }

        // 5) advance: next-next ticket, wait prefetch, publish
        if (tid == 0 && tn < NTILE) s_tk = atomicAdd(&g_tB, 1);
        cp_async_wait_all();
        __syncthreads();                           // (E)
        cur ^= 1;
        t = tn;
    }

    // ================= Counter self-reset (replay-safe) =====================
    __syncthreads();
    if (tid == 0) {
        unsigned d = atomicAdd(&g_done, 1);
        if (d == GRID - 1) {
            g_tA = 0; g_tB = 0; g_barrier = 0;
            __threadfence();
            g_done = 0;
        }
    }
}

// ---------------------------------------------------------------------------
// Launch: In, wtVC, gdiags, GnnPerms, NNsites (metadata order). ONE kernel.
// ---------------------------------------------------------------------------
extern "C" void kernel_launch(void* const* d_in, const int* in_sizes, int n_in,
                              void* d_out, int out_size) {
    const float* In       = (const float*)d_in[0];
    const float* wtVC     = (const float*)d_in[1];
    const float* gdiags   = (const float*)d_in[2];
    const int*   GnnPerms = (const int*)  d_in[3];
    const int*   NNsites  = (const int*)  d_in[4];
    float*       out      = (float*)d_out;

    fused_all_kernel<<<GRID, THREADS>>>(In, wtVC, gdiags, GnnPerms, NNsites, out);
}